// round 10
// baseline (speedup 1.0000x reference)
#include <cuda_runtime.h>
#include <cuda_bf16.h>
#include <math.h>

// ---------------- scratch (device globals; no allocation allowed) -------------
#define BATCH 8192
#define DIN   256
#define H1    512
#define H2    256
#define DOUT  64

#define EDGE_CAP (1 << 21)

__device__ __nv_bfloat16 g_xh[BATCH * DIN];
__device__ __nv_bfloat16 g_xl[BATCH * DIN];
__device__ __nv_bfloat16 g_w1h[H1 * DIN];
__device__ __nv_bfloat16 g_w1l[H1 * DIN];
__device__ __nv_bfloat16 g_w2h[H2 * H1];
__device__ __nv_bfloat16 g_w2l[H2 * H1];
__device__ __nv_bfloat16 g_h1h[BATCH * H1];
__device__ __nv_bfloat16 g_h1l[BATCH * H1];
__device__ float g_h2[BATCH * H2];
__device__ float g_out[BATCH * DOUT];
__device__ float g_nrm[BATCH * DOUT];
__device__ __nv_bfloat16 g_nB[BATCH * DOUT];
__device__ int  g_edge_cnt;
__device__ int2 g_edges[EDGE_CAP];

__device__ __forceinline__ float tanh_fast(float x)
{
    float y;
    asm("tanh.approx.f32 %0, %1;" : "=f"(y) : "f"(x));
    return y;
}

__device__ __forceinline__ unsigned smem_u32(const void* p)
{
    return (unsigned)__cvta_generic_to_shared(p);
}

__device__ __forceinline__ void cp16(void* dst, const void* src)
{
    unsigned d = smem_u32(dst);
    asm volatile("cp.async.ca.shared.global [%0], [%1], 16;" :: "r"(d), "l"(src));
}

// ---------------- fp32 -> bf16 hi/lo split -------------------------------------
__global__ void split_kernel(const float* __restrict__ src,
                             __nv_bfloat16* __restrict__ hi,
                             __nv_bfloat16* __restrict__ lo, int n)
{
    for (int i = blockIdx.x * blockDim.x + threadIdx.x; i < n;
         i += gridDim.x * blockDim.x) {
        float v = src[i];
        __nv_bfloat16 h = __float2bfloat16(v);
        hi[i] = h;
        lo[i] = __float2bfloat16(v - __bfloat162float(h));
    }
}

// ---------------- split-bf16 tensor GEMM, cp.async 2-stage pipeline ------------
// Block: (MT*32) x 128, BK=16. 8 warps: warp_m in {0,1} (MT*16 rows each),
// warp_n in {0..3} (32 cols each). acc += Ah*Wh + Ah*Wl + Al*Wh.
// OUT_MODE 0: bf16 hi/lo out.  OUT_MODE 1: fp32 out.
#define SST2 24   // row stride in bf16 (48B step -> LDSM conflict-free)

template <int K, int OUT_MODE, int MT>
__global__ void __launch_bounds__(256, 2) gemm_split_kernel(
    const __nv_bfloat16* __restrict__ Ah, const __nv_bfloat16* __restrict__ Al,
    const __nv_bfloat16* __restrict__ Wh, const __nv_bfloat16* __restrict__ Wl,
    const float* __restrict__ bias,
    __nv_bfloat16* __restrict__ Ch, __nv_bfloat16* __restrict__ Cl,
    float* __restrict__ Cf, int N)
{
    constexpr int ROWS = MT * 32;
    __shared__ __align__(16) __nv_bfloat16 sAh[2][ROWS * SST2];
    __shared__ __align__(16) __nv_bfloat16 sAl[2][ROWS * SST2];
    __shared__ __align__(16) __nv_bfloat16 sWh[2][128 * SST2];
    __shared__ __align__(16) __nv_bfloat16 sWl[2][128 * SST2];

    const int t    = threadIdx.x;
    const int lane = t & 31;
    const int wid  = t >> 5;
    const int warp_m = wid & 1;
    const int warp_n = wid >> 1;
    const int i0 = blockIdx.x * ROWS;
    const int n0 = blockIdx.y * 128;

    const int lr = t >> 1;
    const int lc = (t & 1) * 8;

    float acc[MT][4][4];
#pragma unroll
    for (int mt = 0; mt < MT; mt++)
#pragma unroll
        for (int nt = 0; nt < 4; nt++)
#pragma unroll
            for (int r = 0; r < 4; r++) acc[mt][nt][r] = 0.0f;

    // prologue: stage 0
    {
        if (t < MT * 64) {
            size_t ga = (size_t)(i0 + lr) * K + lc;
            cp16(&sAh[0][lr * SST2 + lc], Ah + ga);
            cp16(&sAl[0][lr * SST2 + lc], Al + ga);
        }
        size_t gw = (size_t)(n0 + lr) * K + lc;
        cp16(&sWh[0][lr * SST2 + lc], Wh + gw);
        cp16(&sWl[0][lr * SST2 + lc], Wl + gw);
        asm volatile("cp.async.commit_group;");
    }

    constexpr int NIT = K / 16;
    for (int it = 0; it < NIT; it++) {
        if (it + 1 < NIT) {
            int st = (it + 1) & 1, kk = (it + 1) * 16;
            if (t < MT * 64) {
                size_t ga = (size_t)(i0 + lr) * K + kk + lc;
                cp16(&sAh[st][lr * SST2 + lc], Ah + ga);
                cp16(&sAl[st][lr * SST2 + lc], Al + ga);
            }
            size_t gw = (size_t)(n0 + lr) * K + kk + lc;
            cp16(&sWh[st][lr * SST2 + lc], Wh + gw);
            cp16(&sWl[st][lr * SST2 + lc], Wl + gw);
            asm volatile("cp.async.commit_group;");
            asm volatile("cp.async.wait_group 1;");
        } else {
            asm volatile("cp.async.wait_group 0;");
        }
        __syncthreads();

        const int st = it & 1;
        unsigned ah[MT][4], al[MT][4];
#pragma unroll
        for (int mt = 0; mt < MT; mt++) {
            int row = warp_m * (MT * 16) + mt * 16 + (lane & 15);
            int kc  = (lane >> 4) * 8;
            unsigned off = (unsigned)(row * SST2 + kc) * 2u;
            asm volatile(
                "ldmatrix.sync.aligned.m8n8.x4.shared.b16 {%0,%1,%2,%3}, [%4];"
                : "=r"(ah[mt][0]), "=r"(ah[mt][1]), "=r"(ah[mt][2]), "=r"(ah[mt][3])
                : "r"(smem_u32(sAh[st]) + off));
            asm volatile(
                "ldmatrix.sync.aligned.m8n8.x4.shared.b16 {%0,%1,%2,%3}, [%4];"
                : "=r"(al[mt][0]), "=r"(al[mt][1]), "=r"(al[mt][2]), "=r"(al[mt][3])
                : "r"(smem_u32(sAl[st]) + off));
        }
        unsigned bh[2][4], bl[2][4];
#pragma unroll
        for (int h = 0; h < 2; h++) {
            int grp  = lane >> 3;
            int nrow = warp_n * 32 + h * 16 + (grp >> 1) * 8 + (lane & 7);
            int kc   = (grp & 1) * 8;
            unsigned off = (unsigned)(nrow * SST2 + kc) * 2u;
            asm volatile(
                "ldmatrix.sync.aligned.m8n8.x4.shared.b16 {%0,%1,%2,%3}, [%4];"
                : "=r"(bh[h][0]), "=r"(bh[h][1]), "=r"(bh[h][2]), "=r"(bh[h][3])
                : "r"(smem_u32(sWh[st]) + off));
            asm volatile(
                "ldmatrix.sync.aligned.m8n8.x4.shared.b16 {%0,%1,%2,%3}, [%4];"
                : "=r"(bl[h][0]), "=r"(bl[h][1]), "=r"(bl[h][2]), "=r"(bl[h][3])
                : "r"(smem_u32(sWl[st]) + off));
        }
#pragma unroll
        for (int mt = 0; mt < MT; mt++)
#pragma unroll
            for (int nt = 0; nt < 4; nt++) {
                int hh = nt >> 1, p = (nt & 1) * 2;
#define MMA_BF16(AF, B0, B1)                                              \
    asm volatile(                                                          \
        "mma.sync.aligned.m16n8k16.row.col.f32.bf16.bf16.f32 "            \
        "{%0,%1,%2,%3}, {%4,%5,%6,%7}, {%8,%9}, {%0,%1,%2,%3};"           \
        : "+f"(acc[mt][nt][0]), "+f"(acc[mt][nt][1]),                      \
          "+f"(acc[mt][nt][2]), "+f"(acc[mt][nt][3])                       \
        : "r"(AF[mt][0]), "r"(AF[mt][1]), "r"(AF[mt][2]), "r"(AF[mt][3]), \
          "r"(B0), "r"(B1))
                MMA_BF16(ah, bh[hh][p], bh[hh][p + 1]);
                MMA_BF16(ah, bl[hh][p], bl[hh][p + 1]);
                MMA_BF16(al, bh[hh][p], bh[hh][p + 1]);
#undef MMA_BF16
            }
        __syncthreads();
    }

    // epilogue: bias + tanh + store
#pragma unroll
    for (int mt = 0; mt < MT; mt++)
#pragma unroll
        for (int nt = 0; nt < 4; nt++) {
            int gm = i0 + warp_m * (MT * 16) + mt * 16 + (lane >> 2);
            int gn = n0 + warp_n * 32 + nt * 8 + (lane & 3) * 2;
            float bv0 = bias[gn], bv1 = bias[gn + 1];
            float v00 = tanh_fast(acc[mt][nt][0] + bv0);
            float v01 = tanh_fast(acc[mt][nt][1] + bv1);
            float v10 = tanh_fast(acc[mt][nt][2] + bv0);
            float v11 = tanh_fast(acc[mt][nt][3] + bv1);
            if (OUT_MODE == 0) {
                __nv_bfloat16 h00 = __float2bfloat16(v00);
                __nv_bfloat16 h01 = __float2bfloat16(v01);
                __nv_bfloat16 h10 = __float2bfloat16(v10);
                __nv_bfloat16 h11 = __float2bfloat16(v11);
                *reinterpret_cast<__nv_bfloat162*>(Ch + (size_t)gm * N + gn) =
                    __nv_bfloat162(h00, h01);
                *reinterpret_cast<__nv_bfloat162*>(Ch + (size_t)(gm + 8) * N + gn) =
                    __nv_bfloat162(h10, h11);
                *reinterpret_cast<__nv_bfloat162*>(Cl + (size_t)gm * N + gn) =
                    __nv_bfloat162(__float2bfloat16(v00 - __bfloat162float(h00)),
                                   __float2bfloat16(v01 - __bfloat162float(h01)));
                *reinterpret_cast<__nv_bfloat162*>(Cl + (size_t)(gm + 8) * N + gn) =
                    __nv_bfloat162(__float2bfloat16(v10 - __bfloat162float(h10)),
                                   __float2bfloat16(v11 - __bfloat162float(h11)));
            } else {
                *reinterpret_cast<float2*>(Cf + (size_t)gm * N + gn) =
                    make_float2(v00, v01);
                *reinterpret_cast<float2*>(Cf + (size_t)(gm + 8) * N + gn) =
                    make_float2(v10, v11);
            }
        }
}

// ------------- GEMM3 + bias + normalize; writes out, nrm, nB; zeros res + cnt --
__global__ void __launch_bounds__(256) out_norm_kernel(
    const float* __restrict__ A, const float* __restrict__ W3,
    const float* __restrict__ b3, float* __restrict__ res)
{
    __shared__ __align__(16) float As[16][68];
    __shared__ __align__(16) float Ws[16][68];
    __shared__ __align__(16) float outS[64][68];
    __shared__ float rs[64];

    const int t  = threadIdx.x;
    const int tx = t & 15;
    const int ty = t >> 4;
    const int i0 = blockIdx.x * 64;
    const int K  = 256;

    if (blockIdx.x == 0 && t == 0) g_edge_cnt = 0;

    const int lrow = t >> 2;
    const int lk   = (t & 3) * 4;

    float acc[4][4];
#pragma unroll
    for (int r = 0; r < 4; r++)
#pragma unroll
        for (int c = 0; c < 4; c++) acc[r][c] = 0.0f;

    for (int kk = 0; kk < K; kk += 16) {
        float4 av = *reinterpret_cast<const float4*>(A + (size_t)(i0 + lrow) * K + kk + lk);
        float4 wv = *reinterpret_cast<const float4*>(W3 + (size_t)lrow * K + kk + lk);
        __syncthreads();
        As[lk + 0][lrow] = av.x; As[lk + 1][lrow] = av.y;
        As[lk + 2][lrow] = av.z; As[lk + 3][lrow] = av.w;
        Ws[lk + 0][lrow] = wv.x; Ws[lk + 1][lrow] = wv.y;
        Ws[lk + 2][lrow] = wv.z; Ws[lk + 3][lrow] = wv.w;
        __syncthreads();
#pragma unroll
        for (int k = 0; k < 16; k++) {
            float a[4], b[4];
#pragma unroll
            for (int r = 0; r < 4; r++) a[r] = As[k][tx + 16 * r];
#pragma unroll
            for (int c = 0; c < 4; c++) b[c] = Ws[k][ty + 16 * c];
#pragma unroll
            for (int r = 0; r < 4; r++)
#pragma unroll
                for (int c = 0; c < 4; c++) acc[r][c] += a[r] * b[c];
        }
    }

#pragma unroll
    for (int r = 0; r < 4; r++)
#pragma unroll
        for (int c = 0; c < 4; c++)
            outS[tx + 16 * r][ty + 16 * c] = acc[r][c] + b3[ty + 16 * c];
    __syncthreads();

    if (t < 64) {
        float s = 0.0f;
#pragma unroll
        for (int c = 0; c < 64; c++) { float v = outS[t][c]; s += v * v; }
        rs[t] = 1.0f / (sqrtf(s) + 1e-12f);
    }
    __syncthreads();

#pragma unroll
    for (int q = 0; q < 16; q++) {
        int idx = t + 256 * q;
        int i = idx >> 6, c = idx & 63;
        size_t g = (size_t)(i0 + i) * DOUT + c;
        float v = outS[i][c];
        float nv = v * rs[i];
        g_out[g] = v;
        g_nrm[g] = nv;
        g_nB[g]  = __float2bfloat16(nv);
        res[g]   = 0.0f;
    }
}

// ------------- fid: upper-triangular Gram + threshold scan -> edge list --------
// grid (64,64); blocks with tj < ti exit. Off-diagonal hits emit both orderings.
#define CAND_ABS 0.93808315f   // sqrt(0.88)

__global__ void __launch_bounds__(256, 2) fid_kernel()
{
    if (blockIdx.y < blockIdx.x) return;

    __shared__ __align__(16) __nv_bfloat16 At[128 * 72];
    __shared__ __align__(16) __nv_bfloat16 Bt[128 * 72];

    const int t    = threadIdx.x;
    const int lane = t & 31;
    const int wid  = t >> 5;
    const int warp_m = wid & 1;
    const int warp_n = wid >> 1;
    const int i0 = blockIdx.x * 128;
    const int j0 = blockIdx.y * 128;
    const bool offdiag = (blockIdx.y != blockIdx.x);

#pragma unroll
    for (int q = 0; q < 4; q++) {
        int idx = t + 256 * q;
        int r = idx >> 3, c = idx & 7;
        *reinterpret_cast<float4*>(At + r * 72 + c * 8) =
            *reinterpret_cast<const float4*>(g_nB + (size_t)(i0 + r) * 64 + c * 8);
        *reinterpret_cast<float4*>(Bt + r * 72 + c * 8) =
            *reinterpret_cast<const float4*>(g_nB + (size_t)(j0 + r) * 64 + c * 8);
    }
    __syncthreads();

    const unsigned at_base = smem_u32(At);
    const unsigned bt_base = smem_u32(Bt);

    float acc[4][4][4];
#pragma unroll
    for (int mt = 0; mt < 4; mt++)
#pragma unroll
        for (int nt = 0; nt < 4; nt++)
#pragma unroll
            for (int r = 0; r < 4; r++) acc[mt][nt][r] = 0.0f;

#pragma unroll
    for (int ks = 0; ks < 4; ks++) {
        const int k0 = ks * 16;
        unsigned a[4][4];
#pragma unroll
        for (int mt = 0; mt < 4; mt++) {
            int row = warp_m * 64 + mt * 16 + (lane & 15);
            int kc  = k0 + (lane >> 4) * 8;
            unsigned addr = at_base + (unsigned)(row * 72 + kc) * 2u;
            asm volatile(
                "ldmatrix.sync.aligned.m8n8.x4.shared.b16 {%0,%1,%2,%3}, [%4];"
                : "=r"(a[mt][0]), "=r"(a[mt][1]), "=r"(a[mt][2]), "=r"(a[mt][3])
                : "r"(addr));
        }
        unsigned b[2][4];
#pragma unroll
        for (int h = 0; h < 2; h++) {
            int grp  = lane >> 3;
            int nrow = warp_n * 32 + h * 16 + (grp >> 1) * 8 + (lane & 7);
            int kc   = k0 + (grp & 1) * 8;
            unsigned addr = bt_base + (unsigned)(nrow * 72 + kc) * 2u;
            asm volatile(
                "ldmatrix.sync.aligned.m8n8.x4.shared.b16 {%0,%1,%2,%3}, [%4];"
                : "=r"(b[h][0]), "=r"(b[h][1]), "=r"(b[h][2]), "=r"(b[h][3])
                : "r"(addr));
        }
#pragma unroll
        for (int mt = 0; mt < 4; mt++)
#pragma unroll
            for (int nt = 0; nt < 4; nt++) {
                unsigned b0 = b[nt >> 1][(nt & 1) * 2 + 0];
                unsigned b1 = b[nt >> 1][(nt & 1) * 2 + 1];
                asm volatile(
                    "mma.sync.aligned.m16n8k16.row.col.f32.bf16.bf16.f32 "
                    "{%0,%1,%2,%3}, {%4,%5,%6,%7}, {%8,%9}, {%0,%1,%2,%3};"
                    : "+f"(acc[mt][nt][0]), "+f"(acc[mt][nt][1]),
                      "+f"(acc[mt][nt][2]), "+f"(acc[mt][nt][3])
                    : "r"(a[mt][0]), "r"(a[mt][1]), "r"(a[mt][2]), "r"(a[mt][3]),
                      "r"(b0), "r"(b1));
            }
    }

#pragma unroll
    for (int mt = 0; mt < 4; mt++)
#pragma unroll
        for (int nt = 0; nt < 4; nt++)
#pragma unroll
            for (int r = 0; r < 4; r++) {
                if (fabsf(acc[mt][nt][r]) >= CAND_ABS) {
                    int gi = i0 + warp_m * 64 + mt * 16 + (lane >> 2) + ((r >> 1) ? 8 : 0);
                    int gj = j0 + warp_n * 32 + nt * 8 + (lane & 3) * 2 + (r & 1);
                    if (gi != gj) {
                        int e = atomicAdd(&g_edge_cnt, offdiag ? 2 : 1);
                        if (e < EDGE_CAP) g_edges[e] = make_int2(gi, gj);
                        if (offdiag && e + 1 < EDGE_CAP)
                            g_edges[e + 1] = make_int2(gj, gi);
                    }
                }
            }
}

// ------------- edge apply: exact fp32 recheck + sparse accumulate --------------
__global__ void edge_apply_kernel(float* __restrict__ res)
{
    int n = g_edge_cnt;
    if (n > EDGE_CAP) n = EDGE_CAP;
    for (int e = blockIdx.x * blockDim.x + threadIdx.x; e < n;
         e += gridDim.x * blockDim.x) {
        int2 ed = g_edges[e];
        const float4* pa = reinterpret_cast<const float4*>(g_nrm + (size_t)ed.x * DOUT);
        const float4* pb = reinterpret_cast<const float4*>(g_nrm + (size_t)ed.y * DOUT);
        float s = 0.0f;
#pragma unroll
        for (int q = 0; q < 16; q++) {
            float4 xa = pa[q], xb = pb[q];
            s += xa.x * xb.x + xa.y * xb.y + xa.z * xb.z + xa.w * xb.w;
        }
        if (s * s >= 0.9f) {
            const float* oj = g_out + (size_t)ed.y * DOUT;
            float* ri = res + (size_t)ed.x * DOUT;
#pragma unroll
            for (int c = 0; c < DOUT; c++) atomicAdd(&ri[c], oj[c]);
        }
    }
}

// ------------------------------- launch ----------------------------------------
extern "C" void kernel_launch(void* const* d_in, const int* in_sizes, int n_in,
                              void* d_out, int out_size)
{
    const float* x  = (const float*)d_in[0];
    const float* W1 = (const float*)d_in[1];
    const float* b1 = (const float*)d_in[2];
    const float* W2 = (const float*)d_in[3];
    const float* b2 = (const float*)d_in[4];
    const float* W3 = (const float*)d_in[5];
    const float* b3 = (const float*)d_in[6];
    float* out = (float*)d_out;

    __nv_bfloat16 *xh, *xl, *w1h, *w1l, *w2h, *w2l, *h1h, *h1l;
    float *h2p;
    cudaGetSymbolAddress((void**)&xh,  g_xh);
    cudaGetSymbolAddress((void**)&xl,  g_xl);
    cudaGetSymbolAddress((void**)&w1h, g_w1h);
    cudaGetSymbolAddress((void**)&w1l, g_w1l);
    cudaGetSymbolAddress((void**)&w2h, g_w2h);
    cudaGetSymbolAddress((void**)&w2l, g_w2l);
    cudaGetSymbolAddress((void**)&h1h, g_h1h);
    cudaGetSymbolAddress((void**)&h1l, g_h1l);
    cudaGetSymbolAddress((void**)&h2p, g_h2);

    split_kernel<<<512, 256>>>(x,  xh,  xl,  BATCH * DIN);
    split_kernel<<<128, 256>>>(W1, w1h, w1l, H1 * DIN);
    split_kernel<<<128, 256>>>(W2, w2h, w2l, H2 * H1);

    // GEMM1: [8192,256] x [512,256]^T, BM=128 (MT=4), grid 64x4
    gemm_split_kernel<DIN, 0, 4><<<dim3(BATCH / 128, H1 / 128), 256>>>(
        xh, xl, w1h, w1l, b1, h1h, h1l, nullptr, H1);
    // GEMM2: [8192,512] x [256,512]^T, BM=64 (MT=2), grid 128x2 = 256 blocks
    gemm_split_kernel<H1, 1, 2><<<dim3(BATCH / 64, H2 / 128), 256>>>(
        h1h, h1l, w2h, w2l, b2, nullptr, nullptr, h2p, H2);

    out_norm_kernel<<<BATCH / 64, 256>>>(h2p, W3, b3, out);
    fid_kernel<<<dim3(BATCH / 128, BATCH / 128), 256>>>();
    edge_apply_kernel<<<256, 128>>>(out);
}